// round 1
// baseline (speedup 1.0000x reference)
#include <cuda_runtime.h>
#include <math.h>

#define B_ 16
#define S_ 512
#define H_ 768
#define T_ 9
#define D_ 64
#define C_ (T_ * 2 * D_)   // 1152
#define NEG_ 1000000000000.0f

// Scratch (allocation-free rule: __device__ globals)
__device__ float g_Q[(size_t)B_ * T_ * S_ * D_];   // [b,t,s,d]  18.9 MB
__device__ float g_K[(size_t)B_ * T_ * S_ * D_];   // [b,t,s,d]  18.9 MB
__device__ float g_cos[S_ * (D_ / 2)];
__device__ float g_sin[S_ * (D_ / 2)];

// ---------------------------------------------------------------------------
// RoPE angle tables. Reference computes ang = pos * 10000^{-2i/D} in fp32 and
// then cos/sin of that fp32 value. We reproduce that: fp32 angle, accurate
// (double) sin/cos of the fp32 angle.
// ---------------------------------------------------------------------------
__global__ void rope_table_kernel() {
    int idx = blockIdx.x * blockDim.x + threadIdx.x;
    if (idx >= S_ * (D_ / 2)) return;
    int s = idx >> 5;      // / 32
    int i = idx & 31;
    float invf = (float)pow(10000.0, -2.0 * (double)i / (double)D_);
    float ang = (float)s * invf;
    g_cos[idx] = (float)cos((double)ang);
    g_sin[idx] = (float)sin((double)ang);
}

// ---------------------------------------------------------------------------
// GEMM1 + bias + interleaved RoPE, scatter into g_Q / g_K.
// M = B*S = 8192, K = 768, N = 1152. 64x64 tile, BK=16, 256 threads, 4x4/thread.
// ---------------------------------------------------------------------------
__global__ void __launch_bounds__(256) proj_rope_kernel(
    const float* __restrict__ hidden, const float* __restrict__ W,
    const float* __restrict__ bias)
{
    __shared__ float As[16][64 + 4];   // [k][m]
    __shared__ float Bs[16][64 + 4];   // [k][n]

    const int tid = threadIdx.x;
    const int tx = tid & 15, ty = tid >> 4;
    const int row0 = blockIdx.y * 64;
    const int col0 = blockIdx.x * 64;

    const int aRow = tid >> 2;          // 0..63
    const int aK4  = (tid & 3) * 4;     // 0,4,8,12
    const int bK   = tid >> 4;          // 0..15
    const int bCol = (tid & 15) * 4;    // 0..60

    const float* Aptr = hidden + (size_t)(row0 + aRow) * H_ + aK4;
    const float* Bptr = W + (size_t)bK * C_ + col0 + bCol;

    float acc[4][4] = {};

    for (int k0 = 0; k0 < H_; k0 += 16) {
        float4 a = *(const float4*)(Aptr + k0);
        As[aK4 + 0][aRow] = a.x;
        As[aK4 + 1][aRow] = a.y;
        As[aK4 + 2][aRow] = a.z;
        As[aK4 + 3][aRow] = a.w;
        *(float4*)&Bs[bK][bCol] = *(const float4*)(Bptr + (size_t)k0 * C_);
        __syncthreads();

        #pragma unroll
        for (int k = 0; k < 16; k++) {
            float ar[4], br[4];
            #pragma unroll
            for (int r = 0; r < 4; r++) ar[r] = As[k][ty * 4 + r];
            #pragma unroll
            for (int c = 0; c < 4; c++) br[c] = Bs[k][tx * 4 + c];
            #pragma unroll
            for (int r = 0; r < 4; r++)
                #pragma unroll
                for (int c = 0; c < 4; c++)
                    acc[r][c] = fmaf(ar[r], br[c], acc[r][c]);
        }
        __syncthreads();
    }

    // Epilogue: bias + interleaved RoPE, scatter to Q/K scratch.
    const int cbase = col0 + tx * 4;
    #pragma unroll
    for (int r = 0; r < 4; r++) {
        int row = row0 + ty * 4 + r;
        int b = row >> 9;        // / 512
        int s = row & 511;
        #pragma unroll
        for (int p = 0; p < 2; p++) {
            int c = cbase + 2 * p;
            int t = c >> 7;          // / 128
            int j = c & 127;
            int isK = (j >= 64);
            int d = j - (isK ? 64 : 0);
            int i = d >> 1;
            float cv = g_cos[s * 32 + i];
            float sv = g_sin[s * 32 + i];
            float x0 = acc[r][2 * p]     + bias[c];
            float x1 = acc[r][2 * p + 1] + bias[c + 1];
            // x' = x*cos + rotate_half(x)*sin; rotate_half: (2i)->-x[2i+1], (2i+1)->x[2i]
            float y0 = x0 * cv - x1 * sv;
            float y1 = x1 * cv + x0 * sv;
            float* dst = (isK ? g_K : g_Q)
                       + ((size_t)((b * T_ + t) * S_ + s)) * D_ + d;
            dst[0] = y0;
            dst[1] = y1;
        }
    }
}

// ---------------------------------------------------------------------------
// GEMM2: logits[b,t,m,n] = sum_d Q[b,t,m,d]*K[b,t,n,d], masked, * 1/8.
// Per block: one (b,t), 64x64 output tile, full K=64.
// ---------------------------------------------------------------------------
__global__ void __launch_bounds__(256) logits_kernel(
    const int* __restrict__ mask, float* __restrict__ out)
{
    __shared__ float Qs[64][65];   // [d][m]
    __shared__ float Ks[64][65];   // [d][n]

    const int bt = blockIdx.z;
    const int b = bt / T_;
    const int m0 = blockIdx.y * 64;
    const int n0 = blockIdx.x * 64;

    const float* Qp = g_Q + (size_t)bt * S_ * D_;
    const float* Kp = g_K + (size_t)bt * S_ * D_;

    const int tid = threadIdx.x;
    #pragma unroll
    for (int i = 0; i < 4; i++) {
        int idx = tid + i * 256;           // 0..1023
        int r  = idx >> 4;                 // 0..63 (row)
        int c4 = (idx & 15) * 4;           // 0..60 (d)
        float4 q = *(const float4*)&Qp[(size_t)(m0 + r) * D_ + c4];
        Qs[c4 + 0][r] = q.x; Qs[c4 + 1][r] = q.y;
        Qs[c4 + 2][r] = q.z; Qs[c4 + 3][r] = q.w;
        float4 k = *(const float4*)&Kp[(size_t)(n0 + r) * D_ + c4];
        Ks[c4 + 0][r] = k.x; Ks[c4 + 1][r] = k.y;
        Ks[c4 + 2][r] = k.z; Ks[c4 + 3][r] = k.w;
    }
    __syncthreads();

    const int tx = tid & 15, ty = tid >> 4;
    float acc[4][4] = {};
    #pragma unroll
    for (int k = 0; k < 64; k++) {
        float q[4], kk[4];
        #pragma unroll
        for (int r = 0; r < 4; r++) q[r] = Qs[k][ty * 4 + r];
        #pragma unroll
        for (int c = 0; c < 4; c++) kk[c] = Ks[k][tx * 4 + c];
        #pragma unroll
        for (int r = 0; r < 4; r++)
            #pragma unroll
            for (int c = 0; c < 4; c++)
                acc[r][c] = fmaf(q[r], kk[c], acc[r][c]);
    }

    #pragma unroll
    for (int r = 0; r < 4; r++) {
        int m = m0 + ty * 4 + r;
        float4 v;
        float* vp = &v.x;
        #pragma unroll
        for (int c = 0; c < 4; c++) {
            int n = n0 + tx * 4 + c;
            float pm = (float)mask[b * S_ + n];
            float l = acc[r][c];
            l = l * pm - (1.0f - pm) * NEG_;   // padding mask
            if (m > n) l -= NEG_;              // causal (tril, -1)
            vp[c] = l * 0.125f;                // 1/sqrt(64)
        }
        *(float4*)&out[((size_t)bt * S_ + m) * S_ + n0 + tx * 4] = v;
    }
}

// ---------------------------------------------------------------------------
extern "C" void kernel_launch(void* const* d_in, const int* in_sizes, int n_in,
                              void* d_out, int out_size)
{
    const float* hidden = (const float*)d_in[0];   // (16,512,768)
    const float* W      = (const float*)d_in[1];   // (768,1152)
    const float* bias   = (const float*)d_in[2];   // (1152,)
    const int*   mask   = (const int*)d_in[3];     // (16,512)
    float* out = (float*)d_out;                    // (16,9,512,512)

    rope_table_kernel<<<(S_ * 32 + 255) / 256, 256>>>();

    dim3 g1(C_ / 64, (B_ * S_) / 64);              // (18, 128)
    proj_rope_kernel<<<g1, 256>>>(hidden, W, bias);

    dim3 g2(S_ / 64, S_ / 64, B_ * T_);            // (8, 8, 144)
    logits_kernel<<<g2, 256>>>(mask, out);
}

// round 3
// speedup vs baseline: 3.3921x; 3.3921x over previous
#include <cuda_runtime.h>
#include <cuda_bf16.h>
#include <stdint.h>
#include <math.h>

#define B_ 16
#define S_ 512
#define H_ 768
#define T_ 9
#define D_ 64
#define C_ 1152
#define NEG_ 1000000000000.0f

// Scratch (allocation-free rule: __device__ globals). bf16 Q/K: 9.4 MB each.
__device__ __nv_bfloat16 g_Qb[(size_t)B_ * T_ * S_ * D_];   // [b,t,s,d]
__device__ __nv_bfloat16 g_Kb[(size_t)B_ * T_ * S_ * D_];   // [b,t,s,d]
__device__ float g_cos[S_ * 32];
__device__ float g_sin[S_ * 32];

// ---------------------------------------------------------------------------
// helpers
// ---------------------------------------------------------------------------
__device__ __forceinline__ uint32_t bf2(float x, float y) {
    __nv_bfloat162 h = __floats2bfloat162_rn(x, y);
    return *reinterpret_cast<uint32_t*>(&h);
}
__device__ __forceinline__ uint32_t smem_u32(const void* p) {
    return (uint32_t)__cvta_generic_to_shared(p);
}
__device__ __forceinline__ void ldsm_x4(uint32_t* r, uint32_t addr) {
    asm volatile("ldmatrix.sync.aligned.m8n8.x4.shared.b16 {%0,%1,%2,%3}, [%4];"
        : "=r"(r[0]), "=r"(r[1]), "=r"(r[2]), "=r"(r[3]) : "r"(addr));
}
__device__ __forceinline__ void mma16816(float* c, const uint32_t* a, const uint32_t* b) {
    asm volatile(
        "mma.sync.aligned.m16n8k16.row.col.f32.bf16.bf16.f32 "
        "{%0,%1,%2,%3}, {%4,%5,%6,%7}, {%8,%9}, {%0,%1,%2,%3};"
        : "+f"(c[0]), "+f"(c[1]), "+f"(c[2]), "+f"(c[3])
        : "r"(a[0]), "r"(a[1]), "r"(a[2]), "r"(a[3]), "r"(b[0]), "r"(b[1]));
}

// ---------------------------------------------------------------------------
// RoPE tables, fp32. ang = s * 10000^(-2i/64); exp2f/sincosf accuracy is far
// inside the (norm-based) error budget.
// ---------------------------------------------------------------------------
__global__ void rope_table_kernel() {
    int idx = blockIdx.x * blockDim.x + threadIdx.x;
    if (idx >= S_ * 32) return;
    int s = idx >> 5, i = idx & 31;
    float inv = exp2f(-(float)i * (13.287712379549449f / 32.0f)); // log2(1e4)/32
    float ang = (float)s * inv;
    float sv, cv;
    sincosf(ang, &sv, &cv);
    g_cos[idx] = cv;
    g_sin[idx] = sv;
}

// ---------------------------------------------------------------------------
// GEMM1 (M=8192,K=768,N=1152) + bias + interleaved RoPE -> bf16 Q/K scratch.
// Block tile 128x64, BK=32, 256 threads = 8 warps (4m x 2n), warp tile 32x32.
// bf16 mma.sync m16n8k16, fp32 accum.
// ---------------------------------------------------------------------------
__global__ void __launch_bounds__(256) proj_rope_kernel(
    const float* __restrict__ hidden, const float* __restrict__ W,
    const float* __restrict__ bias)
{
    __shared__ __nv_bfloat16 As[128 * 40];  // [m][k], stride 40 (conflict-free ldmatrix)
    __shared__ __nv_bfloat16 Bs[64 * 40];   // [n][k] (W transposed), stride 40

    const int tid = threadIdx.x;
    const int lane = tid & 31;
    const int warp = tid >> 5;
    const int wm = warp >> 1, wn = warp & 1;
    const int row0 = blockIdx.y * 128;
    const int col0 = blockIdx.x * 64;

    float acc[2][4][4];
    #pragma unroll
    for (int a = 0; a < 2; a++)
        #pragma unroll
        for (int bq = 0; bq < 4; bq++)
            #pragma unroll
            for (int cq = 0; cq < 4; cq++) acc[a][bq][cq] = 0.0f;

    const int bkg = tid >> 6;       // 0..3  (k octet)
    const int bn  = tid & 63;       // 0..63 (n within tile)

    for (int k0 = 0; k0 < H_; k0 += 32) {
        // --- A tile: 128x32 fp32 -> bf16 smem, coalesced float4 loads
        #pragma unroll
        for (int i = 0; i < 4; i++) {
            int idx = tid + i * 256;
            int m = idx >> 3, kq = idx & 7;
            const float4 a = *(const float4*)&hidden[(size_t)(row0 + m) * H_ + k0 + kq * 4];
            uint2 p;
            p.x = bf2(a.x, a.y);
            p.y = bf2(a.z, a.w);
            *(uint2*)&As[m * 40 + kq * 4] = p;
        }
        // --- B tile: W[k][n] 32x64 -> Bs[n][k]; 8 coalesced scalar rows/thread,
        //     packed to one 16B store (conflict-free banks)
        {
            const float* wp = &W[(size_t)(k0 + bkg * 8) * C_ + col0 + bn];
            float v[8];
            #pragma unroll
            for (int r = 0; r < 8; r++) v[r] = wp[(size_t)r * C_];
            uint4 p;
            p.x = bf2(v[0], v[1]);
            p.y = bf2(v[2], v[3]);
            p.z = bf2(v[4], v[5]);
            p.w = bf2(v[6], v[7]);
            *(uint4*)&Bs[bn * 40 + bkg * 8] = p;
        }
        __syncthreads();

        #pragma unroll
        for (int ks = 0; ks < 32; ks += 16) {
            uint32_t afr[2][4], bfr[4][2];
            #pragma unroll
            for (int mt = 0; mt < 2; mt++) {
                int r = wm * 32 + mt * 16 + (lane & 15);
                int c = ks + (lane >> 4) * 8;
                ldsm_x4(afr[mt], smem_u32(&As[r * 40 + c]));
            }
            #pragma unroll
            for (int p = 0; p < 2; p++) {
                int n = wn * 32 + p * 16 + ((lane >> 4) & 1) * 8 + (lane & 7);
                int c = ks + ((lane >> 3) & 1) * 8;
                uint32_t t4[4];
                ldsm_x4(t4, smem_u32(&Bs[n * 40 + c]));
                bfr[p * 2 + 0][0] = t4[0]; bfr[p * 2 + 0][1] = t4[1];
                bfr[p * 2 + 1][0] = t4[2]; bfr[p * 2 + 1][1] = t4[3];
            }
            #pragma unroll
            for (int mt = 0; mt < 2; mt++)
                #pragma unroll
                for (int nt = 0; nt < 4; nt++)
                    mma16816(acc[mt][nt], afr[mt], bfr[nt]);
        }
        __syncthreads();
    }

    // Epilogue: bias + interleaved RoPE, scatter bf16 pairs to Q/K scratch.
    // mma frag: c0,c1 = (row, col..col+1); c2,c3 = (row+8, col..col+1); col even.
    #pragma unroll
    for (int nt = 0; nt < 4; nt++) {
        int colg = col0 + wn * 32 + nt * 8 + (lane & 3) * 2;
        int t = colg >> 7;
        int j = colg & 127;
        int isK = j >= 64;
        int d = j & 63;
        int ii = d >> 1;
        float b0v = bias[colg], b1v = bias[colg + 1];
        __nv_bfloat16* base = isK ? g_Kb : g_Qb;
        #pragma unroll
        for (int mt = 0; mt < 2; mt++) {
            #pragma unroll
            for (int h = 0; h < 2; h++) {
                int rowg = row0 + wm * 32 + mt * 16 + (lane >> 2) + h * 8;
                int b = rowg >> 9;
                int s = rowg & 511;
                float cv = g_cos[s * 32 + ii];
                float sv = g_sin[s * 32 + ii];
                float x0 = acc[mt][nt][h * 2 + 0] + b0v;
                float x1 = acc[mt][nt][h * 2 + 1] + b1v;
                float y0 = x0 * cv - x1 * sv;   // even: x*cos - x_odd*sin
                float y1 = x1 * cv + x0 * sv;   // odd : x*cos + x_even*sin
                __nv_bfloat162 o = __floats2bfloat162_rn(y0, y1);
                *(__nv_bfloat162*)&base[((size_t)((b * T_ + t) * S_ + s)) * D_ + d] = o;
            }
        }
    }
}

// ---------------------------------------------------------------------------
// GEMM2: logits[bt,m,n] = Q[bt,m,:] . K[bt,n,:]; 128x128 tile per block,
// full K=64 in smem. bf16 mma.sync, masked fp32 epilogue.
// ---------------------------------------------------------------------------
__global__ void __launch_bounds__(256) logits_kernel(
    const int* __restrict__ mask, float* __restrict__ out)
{
    __shared__ __nv_bfloat16 Qs[128 * 72];  // [m][d], stride 72
    __shared__ __nv_bfloat16 Ks[128 * 72];  // [n][d], stride 72

    const int tid = threadIdx.x;
    const int lane = tid & 31;
    const int warp = tid >> 5;
    const int wm = warp >> 1, wn = warp & 1;   // 4m x 2n warps; warp tile 32x64
    const int bt = blockIdx.z;
    const int b = bt / T_;
    const int m0 = blockIdx.y * 128;
    const int n0 = blockIdx.x * 128;

    const __nv_bfloat16* Qp = g_Qb + (size_t)bt * S_ * D_;
    const __nv_bfloat16* Kp = g_Kb + (size_t)bt * S_ * D_;

    #pragma unroll
    for (int i = 0; i < 4; i++) {
        int idx = tid + i * 256;
        int r = idx >> 3, u = idx & 7;
        *(uint4*)&Qs[r * 72 + u * 8] = *(const uint4*)&Qp[(size_t)(m0 + r) * D_ + u * 8];
        *(uint4*)&Ks[r * 72 + u * 8] = *(const uint4*)&Kp[(size_t)(n0 + r) * D_ + u * 8];
    }
    __syncthreads();

    float acc[2][8][4];
    #pragma unroll
    for (int a = 0; a < 2; a++)
        #pragma unroll
        for (int bq = 0; bq < 8; bq++)
            #pragma unroll
            for (int cq = 0; cq < 4; cq++) acc[a][bq][cq] = 0.0f;

    #pragma unroll
    for (int ks = 0; ks < 4; ks++) {
        uint32_t afr[2][4], bfr[8][2];
        #pragma unroll
        for (int mt = 0; mt < 2; mt++) {
            int r = wm * 32 + mt * 16 + (lane & 15);
            int c = ks * 16 + (lane >> 4) * 8;
            ldsm_x4(afr[mt], smem_u32(&Qs[r * 72 + c]));
        }
        #pragma unroll
        for (int p = 0; p < 4; p++) {
            int n = wn * 64 + p * 16 + ((lane >> 4) & 1) * 8 + (lane & 7);
            int c = ks * 16 + ((lane >> 3) & 1) * 8;
            uint32_t t4[4];
            ldsm_x4(t4, smem_u32(&Ks[n * 72 + c]));
            bfr[p * 2 + 0][0] = t4[0]; bfr[p * 2 + 0][1] = t4[1];
            bfr[p * 2 + 1][0] = t4[2]; bfr[p * 2 + 1][1] = t4[3];
        }
        #pragma unroll
        for (int mt = 0; mt < 2; mt++)
            #pragma unroll
            for (int nt = 0; nt < 8; nt++)
                mma16816(acc[mt][nt], afr[mt], bfr[nt]);
    }

    // Masked epilogue, same op order as reference.
    #pragma unroll
    for (int nt = 0; nt < 8; nt++) {
        int n = n0 + wn * 64 + nt * 8 + (lane & 3) * 2;
        float pm0 = (float)mask[b * S_ + n];
        float pm1 = (float)mask[b * S_ + n + 1];
        #pragma unroll
        for (int mt = 0; mt < 2; mt++) {
            #pragma unroll
            for (int h = 0; h < 2; h++) {
                int m = m0 + wm * 32 + mt * 16 + (lane >> 2) + h * 8;
                float v0 = acc[mt][nt][h * 2 + 0] * pm0 - (1.0f - pm0) * NEG_;
                float v1 = acc[mt][nt][h * 2 + 1] * pm1 - (1.0f - pm1) * NEG_;
                if (m > n)     v0 -= NEG_;
                if (m > n + 1) v1 -= NEG_;
                float2 o = make_float2(v0 * 0.125f, v1 * 0.125f);
                *(float2*)&out[((size_t)bt * S_ + m) * S_ + n] = o;
            }
        }
    }
}

// ---------------------------------------------------------------------------
extern "C" void kernel_launch(void* const* d_in, const int* in_sizes, int n_in,
                              void* d_out, int out_size)
{
    const float* hidden = (const float*)d_in[0];   // (16,512,768)
    const float* W      = (const float*)d_in[1];   // (768,1152)
    const float* bias   = (const float*)d_in[2];   // (1152,)
    const int*   mask   = (const int*)d_in[3];     // (16,512)
    float* out = (float*)d_out;                    // (16,9,512,512)

    rope_table_kernel<<<64, 256>>>();

    dim3 g1(C_ / 64, (B_ * S_) / 128);             // (18, 64)
    proj_rope_kernel<<<g1, 256>>>(hidden, W, bias);

    dim3 g2(S_ / 128, S_ / 128, B_ * T_);          // (4, 4, 144)
    logits_kernel<<<g2, 256>>>(mask, out);
}